// round 1
// baseline (speedup 1.0000x reference)
#include <cuda_runtime.h>
#include <math.h>

namespace {

constexpr int B_  = 16;
constexpr int N_  = 512;
constexpr int K_  = 48;
constexpr int D_  = 128;
constexpr int G_  = 32;
constexpr int H_  = 8;
constexpr int KP1 = 49;   // K + 1 (self)

__global__ void __launch_bounds__(256)
tdt_kernel(const float* __restrict__ positions,
           const int*   __restrict__ z,
           const int*   __restrict__ neighbors,
           const float* __restrict__ nmask,
           const float* __restrict__ embedding,
           const float* __restrict__ filtW,
           const float* __restrict__ filtb,
           const float* __restrict__ Wq,
           const float* __restrict__ Wk,
           const float* __restrict__ Wv,
           const float* __restrict__ Wo,
           float*       __restrict__ out)
{
    __shared__ __align__(16) float sx[D_];          // center embedding
    __shared__ __align__(16) float sq[D_];          // q = x @ Wq
    __shared__ __align__(16) float sp[H_ * D_];     // p[h][d]
    __shared__ __align__(16) float sf[KP1 * G_];    // gaussian features
    __shared__ __align__(16) float skv[KP1 * D_];   // kv_in
    __shared__ __align__(16) float su[H_ * D_];     // attn-weighted kv
    __shared__ __align__(16) float sattn[H_ * 64];  // scores -> attn
    __shared__ float sC[64], slogr[64], smask[64], sagg[D_];
    __shared__ int   szj[64];

    const int atom = blockIdx.x;          // b * N + i
    const int b    = atom >> 9;           // / 512
    const int tid  = threadIdx.x;
    const int d0   = tid & 127;
    const int half = tid >> 7;
    const int lane = tid & 31;
    const int warp = tid >> 5;

    const int zi = z[atom];
    if (tid < D_) sx[tid] = embedding[zi * D_ + tid];

    // ---- Phase A: per-neighbor scalars (r, logr, cutoff, mask, z_j) ----
    if (tid >= 128 && tid < 128 + KP1) {
        const int j = tid - 128;
        float r, mk; int zjv;
        if (j == 0) { r = 0.01f; mk = 1.0f; zjv = zi; }
        else {
            const int nb = neighbors[atom * K_ + j - 1];
            const float dx = positions[(b * N_ + nb) * 3 + 0] - positions[atom * 3 + 0];
            const float dy = positions[(b * N_ + nb) * 3 + 1] - positions[atom * 3 + 1];
            const float dz = positions[(b * N_ + nb) * 3 + 2] - positions[atom * 3 + 2];
            r   = sqrtf(dx * dx + dy * dy + dz * dz + 1e-12f);
            mk  = nmask[atom * K_ + j - 1];
            zjv = z[b * N_ + nb];
        }
        slogr[j] = __logf(r);
        sC[j]    = (r < 5.0f) ? (0.5f * (__cosf(r * 0.6283185307f) + 1.0f)) : 0.0f;
        smask[j] = mk;
        szj[j]   = zjv;
    }
    __syncthreads();

    // ---- Phase B: log-normal gaussian smearing f[j][g] ----
    {
        const float OFF0  = -2.3025850930f;          // log(0.1)
        const float STEP  =  0.1261942905f;          // (log5 - log0.1)/31
        const float COEFF = -0.5f / (STEP * STEP);
        for (int idx = tid; idx < KP1 * G_; idx += 256) {
            const float dlt = slogr[idx >> 5] - (OFF0 + STEP * (float)(idx & 31));
            sf[idx] = __expf(COEFF * dlt * dlt);
        }
    }
    // ---- Phase C: q = x @ Wq (coalesced column reads) ----
    if (tid < D_) {
        float a = 0.f;
        #pragma unroll 4
        for (int e = 0; e < D_; e++) a += sx[e] * Wq[e * D_ + tid];
        sq[tid] = a;
    }
    __syncthreads();

    // ---- Phase D: p[h][d] = sum_{c} Wk[d, h*16+c] * q[h*16+c] ----
    // warp handles 16 rows d; lanes split e; quad-shuffle reduce per head segment
    {
        const float4 qr = *(const float4*)&sq[lane * 4];
        #pragma unroll
        for (int rr = 0; rr < 16; rr++) {
            const int d = warp * 16 + rr;
            const float4 wr = *(const float4*)&Wk[d * D_ + lane * 4];
            float part = wr.x * qr.x + wr.y * qr.y + wr.z * qr.z + wr.w * qr.w;
            part += __shfl_xor_sync(0xffffffffu, part, 1);
            part += __shfl_xor_sync(0xffffffffu, part, 2);
            if ((lane & 3) == 0) sp[(lane >> 2) * D_ + d] = part;
        }
    }

    // ---- Phase E: kv[j][d] = node_j[d] * (f[j]·filtW[:,d] + b[d]) * C[j] ----
    {
        float fw[G_];
        #pragma unroll
        for (int g = 0; g < G_; g++) fw[g] = filtW[g * D_ + d0];
        const float fb = filtb[d0];
        for (int jp = 0; jp < 25; jp++) {
            const int j = jp * 2 + half;
            if (j < KP1) {
                const float4* fj = (const float4*)&sf[j * G_];
                float w = fb;
                #pragma unroll
                for (int g4 = 0; g4 < 8; g4++) {
                    const float4 fv = fj[g4];
                    w += fv.x * fw[4*g4] + fv.y * fw[4*g4+1]
                       + fv.z * fw[4*g4+2] + fv.w * fw[4*g4+3];
                }
                skv[j * D_ + d0] = embedding[szj[j] * D_ + d0] * w * sC[j];
            }
        }
    }
    __syncthreads();

    // ---- Phase F: scores + softmax; warp == head ----
    {
        const int h = warp;
        const float4 pr = *(const float4*)&sp[h * D_ + lane * 4];
        for (int j = 0; j < KP1; j++) {
            const float4 kq = *(const float4*)&skv[j * D_ + lane * 4];
            float part = pr.x * kq.x + pr.y * kq.y + pr.z * kq.z + pr.w * kq.w;
            #pragma unroll
            for (int o = 16; o > 0; o >>= 1)
                part += __shfl_xor_sync(0xffffffffu, part, o);
            if (lane == 0)
                sattn[h * 64 + j] = (smask[j] > 0.f) ? part * 0.25f : -1e9f;
        }
        __syncwarp();
        float a0 = (lane < KP1)      ? sattn[h * 64 + lane]      : -3.0e38f;
        float a1 = (lane + 32 < KP1) ? sattn[h * 64 + lane + 32] : -3.0e38f;
        float m = fmaxf(a0, a1);
        #pragma unroll
        for (int o = 16; o > 0; o >>= 1)
            m = fmaxf(m, __shfl_xor_sync(0xffffffffu, m, o));
        const float e0 = __expf(a0 - m);
        const float e1 = (lane + 32 < KP1) ? __expf(a1 - m) : 0.f;
        float s = e0 + e1;
        #pragma unroll
        for (int o = 16; o > 0; o >>= 1)
            s += __shfl_xor_sync(0xffffffffu, s, o);
        const float inv = 1.0f / s;
        if (lane < KP1)      sattn[h * 64 + lane]      = e0 * inv;
        if (lane + 32 < KP1) sattn[h * 64 + lane + 32] = e1 * inv;
    }
    __syncthreads();

    // ---- Phase G: u[h][d] = sum_j attn[h][j] * kv[j][d] ----
    {
        const int hb = half * 4;
        float a0 = 0.f, a1 = 0.f, a2 = 0.f, a3 = 0.f;
        for (int j = 0; j < KP1; j++) {
            const float kvd = skv[j * D_ + d0];
            a0 += sattn[(hb + 0) * 64 + j] * kvd;
            a1 += sattn[(hb + 1) * 64 + j] * kvd;
            a2 += sattn[(hb + 2) * 64 + j] * kvd;
            a3 += sattn[(hb + 3) * 64 + j] * kvd;
        }
        su[(hb + 0) * D_ + d0] = a0;
        su[(hb + 1) * D_ + d0] = a1;
        su[(hb + 2) * D_ + d0] = a2;
        su[(hb + 3) * D_ + d0] = a3;
    }
    __syncthreads();

    // ---- Phase H: agg[e] = u[head(e)] · Wv[:, e] (coalesced) ----
    if (tid < D_) {
        const int h = tid >> 4;
        float a = 0.f;
        #pragma unroll 4
        for (int d = 0; d < D_; d++) a += su[h * D_ + d] * Wv[d * D_ + tid];
        sagg[tid] = a;
    }
    __syncthreads();

    // ---- Phase I: out = x + agg @ Wo (coalesced) ----
    if (tid < D_) {
        float a = 0.f;
        #pragma unroll 4
        for (int e = 0; e < D_; e++) a += sagg[e] * Wo[e * D_ + tid];
        out[atom * D_ + tid] = sx[tid] + a;
    }
}

} // namespace

extern "C" void kernel_launch(void* const* d_in, const int* in_sizes, int n_in,
                              void* d_out, int out_size) {
    (void)in_sizes; (void)n_in; (void)out_size;
    tdt_kernel<<<B_ * N_, 256>>>(
        (const float*)d_in[0],   // positions
        (const int*)  d_in[1],   // z
        (const int*)  d_in[2],   // neighbors
        (const float*)d_in[3],   // neighbor_mask
        (const float*)d_in[4],   // embedding
        (const float*)d_in[5],   // filt_W
        (const float*)d_in[6],   // filt_b
        (const float*)d_in[7],   // Wq
        (const float*)d_in[8],   // Wk
        (const float*)d_in[9],   // Wv
        (const float*)d_in[10],  // Wo
        (float*)d_out);
}

// round 2
// speedup vs baseline: 1.2929x; 1.2929x over previous
#include <cuda_runtime.h>
#include <math.h>

namespace {

constexpr int B_  = 16;
constexpr int N_  = 512;
constexpr int K_  = 48;
constexpr int D_  = 128;
constexpr int G_  = 32;
constexpr int KP1 = 49;
constexpr int KVS = 132;              // padded row stride (words) for skv
constexpr int KVA = KP1 * KVS;        // 6468 floats per atom kv tile

// dynamic smem layout (float offsets)
constexpr int SKV   = 0;              // 2 * 6468
constexpr int SF    = SKV + 2 * KVA;  // 12936 ; 2*49*32 = 3136
constexpr int SU    = SF;             // alias (sf dead after phase E): 2*1024
constexpr int SATT  = SF + 2048;      // 2*8*52 = 832 (fits inside 3136)
constexpr int SP    = SF + 3136;      // 16072 ; 2*8*128 = 2048
constexpr int SX    = SP + 2048;      // 18120 ; 256
constexpr int SQ    = SX + 256;       // 18376 ; 256
constexpr int SPART = SQ + 256;       // 18632 ; 512
constexpr int SAGG  = SPART + 512;    // 19144 ; 256
constexpr int SC_   = SAGG + 256;     // 19400 ; 2*64
constexpr int SLR   = SC_ + 128;
constexpr int SMK   = SLR + 128;
constexpr int SZJ   = SMK + 128;      // ints
constexpr int SMEM_FLOATS = SZJ + 128;          // 19912
constexpr int SMEM_BYTES  = SMEM_FLOATS * 4;    // 79648

__global__ void __launch_bounds__(256)
tdt_kernel(const float* __restrict__ positions,
           const int*   __restrict__ z,
           const int*   __restrict__ neighbors,
           const float* __restrict__ nmask,
           const float* __restrict__ embedding,
           const float* __restrict__ filtW,
           const float* __restrict__ filtb,
           const float* __restrict__ Wq,
           const float* __restrict__ Wk,
           const float* __restrict__ Wv,
           const float* __restrict__ Wo,
           float*       __restrict__ out)
{
    extern __shared__ __align__(16) float sm[];
    int* smi = (int*)sm;

    const int tid  = threadIdx.x;
    const int lane = tid & 31;
    const int warp = tid >> 5;
    const int c    = tid & 127;       // column / d index
    const int er   = tid >> 7;        // e-range selector / atom selector

    const int atomBase = blockIdx.x * 2;

    // ---- center embeddings for both atoms ----
    {
        const int a = er;
        const int atom = atomBase + a;
        sm[SX + a * 128 + c] = embedding[z[atom] * D_ + c];
    }

    // ---- Phase A: per-neighbor scalars ----
    if (tid < 128) {
        const int a = tid >> 6;
        const int j = tid & 63;
        if (j < KP1) {
            const int atom = atomBase + a;
            const int b    = atom >> 9;
            float r, mk; int zjv;
            if (j == 0) { r = 0.01f; mk = 1.0f; zjv = z[atom]; }
            else {
                const int nb = neighbors[atom * K_ + j - 1];
                const float dx = positions[(b * N_ + nb) * 3 + 0] - positions[atom * 3 + 0];
                const float dy = positions[(b * N_ + nb) * 3 + 1] - positions[atom * 3 + 1];
                const float dz = positions[(b * N_ + nb) * 3 + 2] - positions[atom * 3 + 2];
                r   = sqrtf(dx * dx + dy * dy + dz * dz + 1e-12f);
                mk  = nmask[atom * K_ + j - 1];
                zjv = z[b * N_ + nb];
            }
            sm[SLR + a * 64 + j] = __logf(r);
            sm[SC_ + a * 64 + j] = (r < 5.0f) ? (0.5f * (__cosf(r * 0.6283185307f) + 1.0f)) : 0.0f;
            sm[SMK + a * 64 + j] = mk;
            smi[SZJ + a * 64 + j] = zjv;
        }
    }
    __syncthreads();

    // ---- Phase B: gaussians sf[a][j][g] ----
    {
        const float OFF0  = -2.3025850930f;
        const float STEP  =  0.1261942905f;
        const float COEFF = -0.5f / (STEP * STEP);
        for (int idx = tid; idx < 2 * KP1 * G_; idx += 256) {
            const int a   = idx / (KP1 * G_);
            const int rem = idx - a * (KP1 * G_);
            const int j   = rem >> 5;
            const int g   = rem & 31;
            const float dlt = sm[SLR + a * 64 + j] - (OFF0 + STEP * (float)g);
            sm[SF + a * (KP1 * G_) + rem] = __expf(COEFF * dlt * dlt);
        }
    }

    // ---- Phase C (part): q_a = x_a @ Wq, e-split across halves ----
    {
        float a0 = 0.f, a1 = 0.f;
        const int e0 = er * 64;
        #pragma unroll 4
        for (int e = e0; e < e0 + 64; e++) {
            const float m = Wq[e * D_ + c];
            a0 += sm[SX + e] * m;
            a1 += sm[SX + 128 + e] * m;
        }
        sm[SPART + (er * 2 + 0) * 128 + c] = a0;
        sm[SPART + (er * 2 + 1) * 128 + c] = a1;
    }
    __syncthreads();
    {   // combine
        sm[SQ + er * 128 + c] = sm[SPART + er * 128 + c] + sm[SPART + 256 + er * 128 + c];
    }
    __syncthreads();

    // ---- Phase D: p_a[h][d] = sum_e Wk[d][e] q_a[e] ; warp = 16 rows ----
    {
        const float4 q0 = *(const float4*)&sm[SQ + lane * 4];
        const float4 q1 = *(const float4*)&sm[SQ + 128 + lane * 4];
        #pragma unroll
        for (int rr = 0; rr < 16; rr++) {
            const int d = warp * 16 + rr;
            const float4 wr = *(const float4*)&Wk[d * D_ + lane * 4];
            float p0 = wr.x * q0.x + wr.y * q0.y + wr.z * q0.z + wr.w * q0.w;
            float p1 = wr.x * q1.x + wr.y * q1.y + wr.z * q1.z + wr.w * q1.w;
            p0 += __shfl_xor_sync(0xffffffffu, p0, 1);
            p0 += __shfl_xor_sync(0xffffffffu, p0, 2);
            p1 += __shfl_xor_sync(0xffffffffu, p1, 1);
            p1 += __shfl_xor_sync(0xffffffffu, p1, 2);
            if ((lane & 3) == 0) {
                const int h = lane >> 2;
                sm[SP + h * 128 + d]        = p0;
                sm[SP + 1024 + h * 128 + d] = p1;
            }
        }
    }

    // ---- Phase E: kv tiles for both atoms (reuse fw registers) ----
    {
        float fw[G_];
        #pragma unroll
        for (int g = 0; g < G_; g++) fw[g] = filtW[g * D_ + c];
        const float fb = filtb[c];
        #pragma unroll
        for (int a = 0; a < 2; a++) {
            for (int jp = 0; jp < 25; jp++) {
                const int j = jp * 2 + er;
                if (j < KP1) {
                    const float4* fj = (const float4*)&sm[SF + a * (KP1 * G_) + j * G_];
                    float w = fb;
                    #pragma unroll
                    for (int g4 = 0; g4 < 8; g4++) {
                        const float4 fv = fj[g4];
                        w += fv.x * fw[4*g4] + fv.y * fw[4*g4+1]
                           + fv.z * fw[4*g4+2] + fv.w * fw[4*g4+3];
                    }
                    sm[SKV + a * KVA + j * KVS + c] =
                        embedding[smi[SZJ + a * 64 + j] * D_ + c] * w * sm[SC_ + a * 64 + j];
                }
            }
        }
    }
    __syncthreads();

    // ---- Phase F: scores + softmax ; warp = head, lanes over j, no shuffles ----
    {
        const int h = warp;
        #pragma unroll
        for (int a = 0; a < 2; a++) {
            const float4* pb = (const float4*)&sm[SP + a * 1024 + h * 128];
            #pragma unroll
            for (int rep = 0; rep < 2; rep++) {
                const int j = lane + rep * 32;
                if (j < KP1) {
                    const float4* kvr = (const float4*)&sm[SKV + a * KVA + j * KVS];
                    float4 acc = make_float4(0.f, 0.f, 0.f, 0.f);
                    #pragma unroll 8
                    for (int d4 = 0; d4 < 32; d4++) {
                        const float4 kv = kvr[d4];
                        const float4 pv = pb[d4];
                        acc.x += kv.x * pv.x; acc.y += kv.y * pv.y;
                        acc.z += kv.z * pv.z; acc.w += kv.w * pv.w;
                    }
                    const float s = (acc.x + acc.y) + (acc.z + acc.w);
                    sm[SATT + a * 416 + h * 52 + j] =
                        (sm[SMK + a * 64 + j] > 0.f) ? s * 0.25f : -1e9f;
                }
            }
            __syncwarp();
            // softmax over 49
            float v0 = sm[SATT + a * 416 + h * 52 + lane];
            float v1 = (lane + 32 < KP1) ? sm[SATT + a * 416 + h * 52 + lane + 32] : -3.0e38f;
            float m = fmaxf(v0, v1);
            #pragma unroll
            for (int o = 16; o > 0; o >>= 1)
                m = fmaxf(m, __shfl_xor_sync(0xffffffffu, m, o));
            const float e0 = __expf(v0 - m);
            const float e1 = (lane + 32 < KP1) ? __expf(v1 - m) : 0.f;
            float ssum = e0 + e1;
            #pragma unroll
            for (int o = 16; o > 0; o >>= 1)
                ssum += __shfl_xor_sync(0xffffffffu, ssum, o);
            const float inv = 1.0f / ssum;
            sm[SATT + a * 416 + h * 52 + lane] = e0 * inv;
            if (lane + 32 < KP1)
                sm[SATT + a * 416 + h * 52 + lane + 32] = e1 * inv;
            __syncwarp();
        }
    }
    __syncthreads();

    // ---- Phase G: u_a[h][d] = sum_j attn * kv ; half -> 4 heads ----
    {
        const int hb = er * 4;
        #pragma unroll
        for (int a = 0; a < 2; a++) {
            float a0 = 0.f, a1 = 0.f, a2 = 0.f, a3 = 0.f;
            const float* kvb = &sm[SKV + a * KVA + c];
            const float* at  = &sm[SATT + a * 416];
            for (int j = 0; j < KP1; j++) {
                const float kvd = kvb[j * KVS];
                a0 += at[(hb + 0) * 52 + j] * kvd;
                a1 += at[(hb + 1) * 52 + j] * kvd;
                a2 += at[(hb + 2) * 52 + j] * kvd;
                a3 += at[(hb + 3) * 52 + j] * kvd;
            }
            sm[SU + a * 1024 + (hb + 0) * 128 + c] = a0;
            sm[SU + a * 1024 + (hb + 1) * 128 + c] = a1;
            sm[SU + a * 1024 + (hb + 2) * 128 + c] = a2;
            sm[SU + a * 1024 + (hb + 3) * 128 + c] = a3;
        }
    }
    __syncthreads();

    // ---- Phase H: agg_a[c] = u_a[head(c)] . Wv[:,c] ; e-split ----
    {
        const int h = c >> 4;
        float a0 = 0.f, a1 = 0.f;
        const int d0 = er * 64;
        #pragma unroll 4
        for (int d = d0; d < d0 + 64; d++) {
            const float m = Wv[d * D_ + c];
            a0 += sm[SU + h * 128 + d] * m;
            a1 += sm[SU + 1024 + h * 128 + d] * m;
        }
        sm[SPART + (er * 2 + 0) * 128 + c] = a0;
        sm[SPART + (er * 2 + 1) * 128 + c] = a1;
    }
    __syncthreads();
    sm[SAGG + er * 128 + c] = sm[SPART + er * 128 + c] + sm[SPART + 256 + er * 128 + c];
    __syncthreads();

    // ---- Phase I: out_a = x_a + agg_a @ Wo ; e-split ----
    {
        float a0 = 0.f, a1 = 0.f;
        const int e0 = er * 64;
        #pragma unroll 4
        for (int e = e0; e < e0 + 64; e++) {
            const float m = Wo[e * D_ + c];
            a0 += sm[SAGG + e] * m;
            a1 += sm[SAGG + 128 + e] * m;
        }
        sm[SPART + (er * 2 + 0) * 128 + c] = a0;
        sm[SPART + (er * 2 + 1) * 128 + c] = a1;
    }
    __syncthreads();
    {
        const int a = er;
        const float v = sm[SPART + a * 128 + c] + sm[SPART + 256 + a * 128 + c];
        out[(atomBase + a) * D_ + c] = sm[SX + a * 128 + c] + v;
    }
}

} // namespace

extern "C" void kernel_launch(void* const* d_in, const int* in_sizes, int n_in,
                              void* d_out, int out_size) {
    (void)in_sizes; (void)n_in; (void)out_size;
    cudaFuncSetAttribute(tdt_kernel,
                         cudaFuncAttributeMaxDynamicSharedMemorySize, SMEM_BYTES);
    tdt_kernel<<<B_ * N_ / 2, 256, SMEM_BYTES>>>(
        (const float*)d_in[0],   // positions
        (const int*)  d_in[1],   // z
        (const int*)  d_in[2],   // neighbors
        (const float*)d_in[3],   // neighbor_mask
        (const float*)d_in[4],   // embedding
        (const float*)d_in[5],   // filt_W
        (const float*)d_in[6],   // filt_b
        (const float*)d_in[7],   // Wq
        (const float*)d_in[8],   // Wk
        (const float*)d_in[9],   // Wv
        (const float*)d_in[10],  // Wo
        (float*)d_out);
}

// round 3
// speedup vs baseline: 2.0268x; 1.5676x over previous
#include <cuda_runtime.h>
#include <cuda_fp16.h>
#include <math.h>

namespace {

constexpr int B_  = 16;
constexpr int N_  = 512;
constexpr int K_  = 48;
constexpr int D_  = 128;
constexpr int G_  = 32;
constexpr int KP1 = 49;

constexpr int KVH  = 136;             // half stride per kv row
constexpr int KVAH = KP1 * KVH;       // 6664 halfs per atom
// word (float) offsets in dynamic smem
constexpr int SKV   = 0;                       // 2*6664 halfs = 6664 words
constexpr int SF    = SKV + 6664;              // gaussians 2*49*32 = 3136 w
constexpr int SSC   = SF;                      // alias: score partials 2048 w
constexpr int SU    = SF;                      // alias: u, stride 132, 2*1056 w
constexpr int SATT  = SF + 2112;               // attn 2*8*52 = 832 w
constexpr int SP    = SF + 3136;               // p, stride 132: 2*1056 = 2112 w
constexpr int SX    = SP + 2112;               // 256
constexpr int SQ    = SX + 256;                // 256
constexpr int SPART = SQ + 256;                // 512
constexpr int SAGG  = SPART + 512;             // 256
constexpr int SC_   = SAGG + 256;              // 128
constexpr int SLR   = SC_ + 128;               // 128
constexpr int SMK   = SLR + 128;               // 128
constexpr int SZJ   = SMK + 128;               // 128 (ints)
constexpr int SMEM_FLOATS = SZJ + 128;         // 13704
constexpr int SMEM_BYTES  = SMEM_FLOATS * 4;   // 54816

__global__ void __launch_bounds__(256, 4)
tdt_kernel(const float* __restrict__ positions,
           const int*   __restrict__ z,
           const int*   __restrict__ neighbors,
           const float* __restrict__ nmask,
           const float* __restrict__ embedding,
           const float* __restrict__ filtW,
           const float* __restrict__ filtb,
           const float* __restrict__ Wq,
           const float* __restrict__ Wk,
           const float* __restrict__ Wv,
           const float* __restrict__ Wo,
           float*       __restrict__ out)
{
    extern __shared__ __align__(16) float sm[];
    int*    smi = (int*)sm;
    __half* kvh = (__half*)sm;        // SKV region in half units: offset SKV*2

    const int tid  = threadIdx.x;
    const int lane = tid & 31;
    const int warp = tid >> 5;
    const int c    = tid & 127;
    const int er   = tid >> 7;

    const int atomBase = blockIdx.x * 2;

    // center embeddings
    sm[SX + er * 128 + c] = embedding[z[atomBase + er] * D_ + c];

    // ---- Phase A: per-neighbor scalars ----
    if (tid < 128) {
        const int a = tid >> 6;
        const int j = tid & 63;
        if (j < KP1) {
            const int atom = atomBase + a;
            const int b    = atom >> 9;
            float r, mk; int zjv;
            if (j == 0) { r = 0.01f; mk = 1.0f; zjv = z[atom]; }
            else {
                const int nb = neighbors[atom * K_ + j - 1];
                const float dx = positions[(b * N_ + nb) * 3 + 0] - positions[atom * 3 + 0];
                const float dy = positions[(b * N_ + nb) * 3 + 1] - positions[atom * 3 + 1];
                const float dz = positions[(b * N_ + nb) * 3 + 2] - positions[atom * 3 + 2];
                r   = sqrtf(dx * dx + dy * dy + dz * dz + 1e-12f);
                mk  = nmask[atom * K_ + j - 1];
                zjv = z[b * N_ + nb];
            }
            sm[SLR + a * 64 + j] = __logf(r);
            sm[SC_ + a * 64 + j] = (r < 5.0f) ? (0.5f * (__cosf(r * 0.6283185307f) + 1.0f)) : 0.0f;
            sm[SMK + a * 64 + j] = mk;
            smi[SZJ + a * 64 + j] = zjv;
        }
    }
    __syncthreads();

    // ---- Phase B: gaussians ----
    {
        const float OFF0  = -2.3025850930f;
        const float STEP  =  0.1261942905f;
        const float COEFF = -0.5f / (STEP * STEP);
        for (int idx = tid; idx < 2 * KP1 * G_; idx += 256) {
            const int a   = idx / (KP1 * G_);
            const int rem = idx - a * (KP1 * G_);
            const float dlt = sm[SLR + a * 64 + (rem >> 5)] - (OFF0 + STEP * (float)(rem & 31));
            sm[SF + a * (KP1 * G_) + rem] = __expf(COEFF * dlt * dlt);
        }
    }
    // ---- Phase C: q = x @ Wq, e-split ----
    {
        float a0 = 0.f, a1 = 0.f;
        const int e0 = er * 64;
        #pragma unroll 4
        for (int e = e0; e < e0 + 64; e++) {
            const float m = Wq[e * D_ + c];
            a0 += sm[SX + e] * m;
            a1 += sm[SX + 128 + e] * m;
        }
        sm[SPART + (er * 2 + 0) * 128 + c] = a0;
        sm[SPART + (er * 2 + 1) * 128 + c] = a1;
    }
    __syncthreads();
    sm[SQ + er * 128 + c] = sm[SPART + er * 128 + c] + sm[SPART + 256 + er * 128 + c];
    __syncthreads();

    // ---- Phase D: p_a[h][d] = sum_e Wk[d][e] q_a[e] ----
    {
        const float4 q0 = *(const float4*)&sm[SQ + lane * 4];
        const float4 q1 = *(const float4*)&sm[SQ + 128 + lane * 4];
        #pragma unroll
        for (int rr = 0; rr < 16; rr++) {
            const int d = warp * 16 + rr;
            const float4 wr = *(const float4*)&Wk[d * D_ + lane * 4];
            float p0 = wr.x * q0.x + wr.y * q0.y + wr.z * q0.z + wr.w * q0.w;
            float p1 = wr.x * q1.x + wr.y * q1.y + wr.z * q1.z + wr.w * q1.w;
            p0 += __shfl_xor_sync(0xffffffffu, p0, 1);
            p0 += __shfl_xor_sync(0xffffffffu, p0, 2);
            p1 += __shfl_xor_sync(0xffffffffu, p1, 1);
            p1 += __shfl_xor_sync(0xffffffffu, p1, 2);
            if ((lane & 3) == 0) {
                const int h = lane >> 2;
                sm[SP + h * 132 + d]        = p0;
                sm[SP + 1056 + h * 132 + d] = p1;
            }
        }
    }

    // ---- Phase E: kv tiles (fp16) ----
    {
        float fw[G_];
        #pragma unroll
        for (int g = 0; g < G_; g++) fw[g] = filtW[g * D_ + c];
        const float fb = filtb[c];
        #pragma unroll
        for (int a = 0; a < 2; a++) {
            for (int jp = 0; jp < 25; jp++) {
                const int j = jp * 2 + er;
                if (j < KP1) {
                    const float4* fj = (const float4*)&sm[SF + a * (KP1 * G_) + j * G_];
                    float w = fb;
                    #pragma unroll
                    for (int g4 = 0; g4 < 8; g4++) {
                        const float4 fv = fj[g4];
                        w += fv.x * fw[4*g4] + fv.y * fw[4*g4+1]
                           + fv.z * fw[4*g4+2] + fv.w * fw[4*g4+3];
                    }
                    const float v = embedding[smi[SZJ + a * 64 + j] * D_ + c]
                                  * w * sm[SC_ + a * 64 + j];
                    kvh[SKV * 2 + a * KVAH + j * KVH + c] = __float2half(v);
                }
            }
        }
    }
    __syncthreads();

    // ---- Phase F: partial scores; kv tile read ONCE ----
    {
        const int task  = warp >> 1;        // a = task>>1, rep = task&1
        const int a     = task >> 1;
        const int rep   = task & 1;
        const int dhalf = warp & 1;
        const int j     = rep * 32 + lane;
        float acc[8];
        #pragma unroll
        for (int h = 0; h < 8; h++) acc[h] = 0.f;
        if (j < KP1) {
            const uint4* kvr = (const uint4*)&kvh[SKV * 2 + a * KVAH + j * KVH + dhalf * 64];
            const float* pb  = &sm[SP + a * 1056 + dhalf * 64];
            #pragma unroll
            for (int c8 = 0; c8 < 8; c8++) {
                const uint4 raw = kvr[c8];
                const float2 f01 = __half22float2(*(const __half2*)&raw.x);
                const float2 f23 = __half22float2(*(const __half2*)&raw.y);
                const float2 f45 = __half22float2(*(const __half2*)&raw.z);
                const float2 f67 = __half22float2(*(const __half2*)&raw.w);
                #pragma unroll
                for (int h = 0; h < 8; h++) {
                    const float4 p0 = *(const float4*)&pb[h * 132 + c8 * 8];
                    const float4 p1 = *(const float4*)&pb[h * 132 + c8 * 8 + 4];
                    acc[h] += f01.x*p0.x + f01.y*p0.y + f23.x*p0.z + f23.y*p0.w
                            + f45.x*p1.x + f45.y*p1.y + f67.x*p1.z + f67.y*p1.w;
                }
            }
        }
        #pragma unroll
        for (int h = 0; h < 8; h++)
            sm[SSC + ((task * 2 + dhalf) * 8 + h) * 32 + lane] = acc[h];
    }
    __syncthreads();

    // ---- softmax: warp = head ----
    {
        const int h = warp;
        #pragma unroll
        for (int a = 0; a < 2; a++) {
            const int t0 = a * 2, t1 = a * 2 + 1;
            float v0 = sm[SSC + ((t0*2+0)*8 + h)*32 + lane]
                     + sm[SSC + ((t0*2+1)*8 + h)*32 + lane];
            float v1 = (lane < 17) ? sm[SSC + ((t1*2+0)*8 + h)*32 + lane]
                                   + sm[SSC + ((t1*2+1)*8 + h)*32 + lane] : 0.f;
            v0 = (sm[SMK + a * 64 + lane] > 0.f) ? v0 * 0.25f : -1e9f;
            const int j1 = lane + 32;
            if (j1 < KP1) v1 = (sm[SMK + a * 64 + j1] > 0.f) ? v1 * 0.25f : -1e9f;
            else          v1 = -3.0e38f;
            float m = fmaxf(v0, v1);
            #pragma unroll
            for (int o = 16; o > 0; o >>= 1)
                m = fmaxf(m, __shfl_xor_sync(0xffffffffu, m, o));
            const float e0 = __expf(v0 - m);
            const float e1 = (j1 < KP1) ? __expf(v1 - m) : 0.f;
            float ssum = e0 + e1;
            #pragma unroll
            for (int o = 16; o > 0; o >>= 1)
                ssum += __shfl_xor_sync(0xffffffffu, ssum, o);
            const float inv = 1.0f / ssum;
            sm[SATT + a * 416 + h * 52 + lane] = e0 * inv;
            if (j1 < KP1) sm[SATT + a * 416 + h * 52 + j1] = e1 * inv;
        }
    }
    __syncthreads();

    // ---- Phase G: u[a][h][c] = sum_j attn * kv ; thread = (atom, c), 8 heads ----
    {
        const int a = er;
        const __half* kvc = &kvh[SKV * 2 + a * KVAH + c];
        const float*  at  = &sm[SATT + a * 416];
        float acc[8];
        #pragma unroll
        for (int h = 0; h < 8; h++) acc[h] = 0.f;
        for (int j = 0; j < KP1; j++) {
            const float kvd = __half2float(kvc[j * KVH]);
            #pragma unroll
            for (int h = 0; h < 8; h++) acc[h] += at[h * 52 + j] * kvd;
        }
        #pragma unroll
        for (int h = 0; h < 8; h++) sm[SU + a * 1056 + h * 132 + c] = acc[h];
    }
    __syncthreads();

    // ---- Phase H: agg_a[c] = u_a[head(c)] . Wv[:,c] ; e-split ----
    {
        const int h = c >> 4;
        float a0 = 0.f, a1 = 0.f;
        const int d0 = er * 64;
        #pragma unroll 4
        for (int d = d0; d < d0 + 64; d++) {
            const float m = Wv[d * D_ + c];
            a0 += sm[SU + h * 132 + d] * m;
            a1 += sm[SU + 1056 + h * 132 + d] * m;
        }
        sm[SPART + (er * 2 + 0) * 128 + c] = a0;
        sm[SPART + (er * 2 + 1) * 128 + c] = a1;
    }
    __syncthreads();
    sm[SAGG + er * 128 + c] = sm[SPART + er * 128 + c] + sm[SPART + 256 + er * 128 + c];
    __syncthreads();

    // ---- Phase I: out = x + agg @ Wo ; e-split ----
    {
        float a0 = 0.f, a1 = 0.f;
        const int e0 = er * 64;
        #pragma unroll 4
        for (int e = e0; e < e0 + 64; e++) {
            const float m = Wo[e * D_ + c];
            a0 += sm[SAGG + e] * m;
            a1 += sm[SAGG + 128 + e] * m;
        }
        sm[SPART + (er * 2 + 0) * 128 + c] = a0;
        sm[SPART + (er * 2 + 1) * 128 + c] = a1;
    }
    __syncthreads();
    {
        const float v = sm[SPART + er * 128 + c] + sm[SPART + 256 + er * 128 + c];
        out[(atomBase + er) * D_ + c] = sm[SX + er * 128 + c] + v;
    }
}

} // namespace

extern "C" void kernel_launch(void* const* d_in, const int* in_sizes, int n_in,
                              void* d_out, int out_size) {
    (void)in_sizes; (void)n_in; (void)out_size;
    cudaFuncSetAttribute(tdt_kernel,
                         cudaFuncAttributeMaxDynamicSharedMemorySize, SMEM_BYTES);
    tdt_kernel<<<B_ * N_ / 2, 256, SMEM_BYTES>>>(
        (const float*)d_in[0],   // positions
        (const int*)  d_in[1],   // z
        (const int*)  d_in[2],   // neighbors
        (const float*)d_in[3],   // neighbor_mask
        (const float*)d_in[4],   // embedding
        (const float*)d_in[5],   // filt_W
        (const float*)d_in[6],   // filt_b
        (const float*)d_in[7],   // Wq
        (const float*)d_in[8],   // Wk
        (const float*)d_in[9],   // Wv
        (const float*)d_in[10],  // Wo
        (float*)d_out);
}

// round 5
// speedup vs baseline: 2.3072x; 1.1383x over previous
#include <cuda_runtime.h>
#include <cuda_fp16.h>
#include <math.h>

namespace {

constexpr int B_  = 16;
constexpr int N_  = 512;
constexpr int K_  = 48;
constexpr int D_  = 128;
constexpr int G_  = 32;
constexpr int KP1 = 49;

constexpr int KVH  = 136;             // half stride per kv row
constexpr int KVAH = KP1 * KVH;       // halfs per atom kv tile

// word offsets in dynamic smem
constexpr int SKV   = 0;              // kv 2*6664 halfs = 6664 w ; alias: partials 2048 w
constexpr int SF    = 6664;           // gaussians 2*49*32 = 3136 w  [B..E]
constexpr int SSC   = 6664;           // score partials 2048 w       [F..softmax]
constexpr int SATT  = 8776;           // attn transposed 2*49*12=1176 [softmax..G]
constexpr int SU    = 6664;           // u 2*8*132 = 2112 w          [G..H]
constexpr int SP    = 9952;           // p 2*8*132 = 2112 w          [D..F]
constexpr int SX    = 12064;          // 256
constexpr int SQ    = 12320;          // 256
constexpr int SAGG  = 12576;          // 256
constexpr int SC_   = 12832;          // 128
constexpr int SLR   = 12960;          // 128
constexpr int SMK   = 13088;          // 128
constexpr int SZJ   = 13216;          // 128 ints
constexpr int SMEM_FLOATS = 13344;
constexpr int SMEM_BYTES  = SMEM_FLOATS * 4;   // 53376

__global__ void __launch_bounds__(256, 4)
tdt_kernel(const float* __restrict__ positions,
           const int*   __restrict__ z,
           const int*   __restrict__ neighbors,
           const float* __restrict__ nmask,
           const float* __restrict__ embedding,
           const float* __restrict__ filtW,
           const float* __restrict__ filtb,
           const float* __restrict__ Wq,
           const float* __restrict__ Wk,
           const float* __restrict__ Wv,
           const float* __restrict__ Wo,
           float*       __restrict__ out)
{
    extern __shared__ __align__(16) float sm[];
    int*    smi = (int*)sm;
    __half* kvh = (__half*)sm;

    const int tid  = threadIdx.x;
    const int lane = tid & 31;
    const int warp = tid >> 5;
    const int c    = tid & 127;
    const int er   = tid >> 7;
    const int c4   = tid & 31;        // column quad id for GEMV phases
    const int g8   = tid >> 5;        // e/d octave for GEMV phases
    const int cc   = c4 * 4;

    const int atomBase = blockIdx.x * 2;

    // center embeddings
    sm[SX + er * 128 + c] = embedding[z[atomBase + er] * D_ + c];

    // ---- Phase A: per-neighbor scalars ----
    if (tid < 128) {
        const int a = tid >> 6;
        const int j = tid & 63;
        if (j < KP1) {
            const int atom = atomBase + a;
            const int b    = atom >> 9;
            float r, mk; int zjv;
            if (j == 0) { r = 0.01f; mk = 1.0f; zjv = z[atom]; }
            else {
                const int nb = neighbors[atom * K_ + j - 1];
                const float dx = positions[(b * N_ + nb) * 3 + 0] - positions[atom * 3 + 0];
                const float dy = positions[(b * N_ + nb) * 3 + 1] - positions[atom * 3 + 1];
                const float dz = positions[(b * N_ + nb) * 3 + 2] - positions[atom * 3 + 2];
                r   = sqrtf(dx * dx + dy * dy + dz * dz + 1e-12f);
                mk  = nmask[atom * K_ + j - 1];
                zjv = z[b * N_ + nb];
            }
            sm[SLR + a * 64 + j] = __logf(r);
            sm[SC_ + a * 64 + j] = (r < 5.0f) ? (0.5f * (__cosf(r * 0.6283185307f) + 1.0f)) : 0.0f;
            sm[SMK + a * 64 + j] = mk;
            smi[SZJ + a * 64 + j] = zjv;
        }
    }
    __syncthreads();

    // ---- Phase B: gaussians ----
    {
        const float OFF0  = -2.3025850930f;
        const float STEP  =  0.1261942905f;
        const float COEFF = -0.5f / (STEP * STEP);
        for (int idx = tid; idx < 2 * KP1 * G_; idx += 256) {
            const int a   = idx / (KP1 * G_);
            const int rem = idx - a * (KP1 * G_);
            const float dlt = sm[SLR + a * 64 + (rem >> 5)] - (OFF0 + STEP * (float)(rem & 31));
            sm[SF + a * (KP1 * G_) + rem] = __expf(COEFF * dlt * dlt);
        }
    }
    {   // C-mult: thread (g8 = e-octave, c4): partials over 16 e for 4 cols x 2 atoms
        float4 a0 = make_float4(0.f,0.f,0.f,0.f), a1 = make_float4(0.f,0.f,0.f,0.f);
        #pragma unroll
        for (int i4 = 0; i4 < 4; i4++) {
            const float4 x0 = *(const float4*)&sm[SX + g8 * 16 + i4 * 4];
            const float4 x1 = *(const float4*)&sm[SX + 128 + g8 * 16 + i4 * 4];
            #pragma unroll
            for (int t = 0; t < 4; t++) {
                const int e = g8 * 16 + i4 * 4 + t;
                const float4 wv = *(const float4*)&Wq[e * 128 + cc];
                const float xs0 = (t==0)?x0.x:(t==1)?x0.y:(t==2)?x0.z:x0.w;
                const float xs1 = (t==0)?x1.x:(t==1)?x1.y:(t==2)?x1.z:x1.w;
                a0.x += xs0*wv.x; a0.y += xs0*wv.y; a0.z += xs0*wv.z; a0.w += xs0*wv.w;
                a1.x += xs1*wv.x; a1.y += xs1*wv.y; a1.z += xs1*wv.z; a1.w += xs1*wv.w;
            }
        }
        *(float4*)&sm[SKV + g8 * 256 + cc]       = a0;
        *(float4*)&sm[SKV + g8 * 256 + 128 + cc] = a1;
    }
    __syncthreads();

    // ---- C-reduce -> q ----
    {
        float s = 0.f;
        #pragma unroll
        for (int e8 = 0; e8 < 8; e8++) s += sm[SKV + e8 * 256 + er * 128 + c];
        sm[SQ + er * 128 + c] = s;
    }
    __syncthreads();

    // ---- Phase D: p_a[h][d] = sum_e Wk[d][e] q_a[e] ----
    {
        const float4 q0 = *(const float4*)&sm[SQ + lane * 4];
        const float4 q1 = *(const float4*)&sm[SQ + 128 + lane * 4];
        #pragma unroll
        for (int rr = 0; rr < 16; rr++) {
            const int d = warp * 16 + rr;
            const float4 wr = *(const float4*)&Wk[d * D_ + lane * 4];
            float p0 = wr.x * q0.x + wr.y * q0.y + wr.z * q0.z + wr.w * q0.w;
            float p1 = wr.x * q1.x + wr.y * q1.y + wr.z * q1.z + wr.w * q1.w;
            p0 += __shfl_xor_sync(0xffffffffu, p0, 1);
            p0 += __shfl_xor_sync(0xffffffffu, p0, 2);
            p1 += __shfl_xor_sync(0xffffffffu, p1, 1);
            p1 += __shfl_xor_sync(0xffffffffu, p1, 2);
            if ((lane & 3) == 0) {
                const int h = lane >> 2;
                sm[SP + h * 132 + d]        = p0;
                sm[SP + 1056 + h * 132 + d] = p1;
            }
        }
    }

    // ---- Phase E: kv tiles (fp16) ----
    {
        float fw[G_];
        #pragma unroll
        for (int g = 0; g < G_; g++) fw[g] = filtW[g * D_ + c];
        const float fb = filtb[c];
        #pragma unroll
        for (int a = 0; a < 2; a++) {
            for (int jp = 0; jp < 25; jp++) {
                const int j = jp * 2 + er;
                if (j < KP1) {
                    const float4* fj = (const float4*)&sm[SF + a * (KP1 * G_) + j * G_];
                    float w = fb;
                    #pragma unroll
                    for (int g4 = 0; g4 < 8; g4++) {
                        const float4 fv = fj[g4];
                        w += fv.x * fw[4*g4] + fv.y * fw[4*g4+1]
                           + fv.z * fw[4*g4+2] + fv.w * fw[4*g4+3];
                    }
                    const float v = embedding[smi[SZJ + a * 64 + j] * D_ + c]
                                  * w * sm[SC_ + a * 64 + j];
                    kvh[SKV * 2 + a * KVAH + j * KVH + c] = __float2half(v);
                }
            }
        }
    }
    __syncthreads();

    // ---- Phase F: partial scores; kv read once ----
    {
        const int task  = warp >> 1;
        const int a     = task >> 1;
        const int rep   = task & 1;
        const int dhalf = warp & 1;
        const int j     = rep * 32 + lane;
        float acc[8];
        #pragma unroll
        for (int h = 0; h < 8; h++) acc[h] = 0.f;
        if (j < KP1) {
            const uint4* kvr = (const uint4*)&kvh[SKV * 2 + a * KVAH + j * KVH + dhalf * 64];
            const float* pb  = &sm[SP + a * 1056 + dhalf * 64];
            #pragma unroll
            for (int c8 = 0; c8 < 8; c8++) {
                const uint4 raw = kvr[c8];
                const float2 f01 = __half22float2(*(const __half2*)&raw.x);
                const float2 f23 = __half22float2(*(const __half2*)&raw.y);
                const float2 f45 = __half22float2(*(const __half2*)&raw.z);
                const float2 f67 = __half22float2(*(const __half2*)&raw.w);
                #pragma unroll
                for (int h = 0; h < 8; h++) {
                    const float4 p0 = *(const float4*)&pb[h * 132 + c8 * 8];
                    const float4 p1 = *(const float4*)&pb[h * 132 + c8 * 8 + 4];
                    acc[h] += f01.x*p0.x + f01.y*p0.y + f23.x*p0.z + f23.y*p0.w
                            + f45.x*p1.x + f45.y*p1.y + f67.x*p1.z + f67.y*p1.w;
                }
            }
        }
        #pragma unroll
        for (int h = 0; h < 8; h++)
            sm[SSC + ((task * 2 + dhalf) * 8 + h) * 32 + lane] = acc[h];
    }
    __syncthreads();

    // ---- softmax: warp = head; writes TRANSPOSED attn [j][h] stride 12 ----
    {
        const int h = warp;
        #pragma unroll
        for (int a = 0; a < 2; a++) {
            const int t0 = a * 2, t1 = a * 2 + 1;
            float v0 = sm[SSC + ((t0*2+0)*8 + h)*32 + lane]
                     + sm[SSC + ((t0*2+1)*8 + h)*32 + lane];
            float v1 = (lane < 17) ? sm[SSC + ((t1*2+0)*8 + h)*32 + lane]
                                   + sm[SSC + ((t1*2+1)*8 + h)*32 + lane] : 0.f;
            v0 = (sm[SMK + a * 64 + lane] > 0.f) ? v0 * 0.25f : -1e9f;
            const int j1 = lane + 32;
            if (j1 < KP1) v1 = (sm[SMK + a * 64 + j1] > 0.f) ? v1 * 0.25f : -1e9f;
            else          v1 = -3.0e38f;
            float m = fmaxf(v0, v1);
            #pragma unroll
            for (int o = 16; o > 0; o >>= 1)
                m = fmaxf(m, __shfl_xor_sync(0xffffffffu, m, o));
            const float e0 = __expf(v0 - m);
            const float e1 = (j1 < KP1) ? __expf(v1 - m) : 0.f;
            float ssum = e0 + e1;
            #pragma unroll
            for (int o = 16; o > 0; o >>= 1)
                ssum += __shfl_xor_sync(0xffffffffu, ssum, o);
            const float inv = 1.0f / ssum;
            sm[SATT + a * 588 + lane * 12 + h] = e0 * inv;
            if (j1 < KP1) sm[SATT + a * 588 + j1 * 12 + h] = e1 * inv;
        }
    }
    __syncthreads();

    // ---- Phase G: u[a][h][c] = sum_j attn[j][h] * kv[j][c] ----
    {
        const int a = er;
        const __half* kvc = &kvh[SKV * 2 + a * KVAH + c];
        const float*  atb = &sm[SATT + a * 588];
        float acc[8];
        #pragma unroll
        for (int h = 0; h < 8; h++) acc[h] = 0.f;
        #pragma unroll 7
        for (int j = 0; j < KP1; j++) {
            const float4 t0 = *(const float4*)&atb[j * 12];
            const float4 t1 = *(const float4*)&atb[j * 12 + 4];
            const float kvd = __half2float(kvc[j * KVH]);
            acc[0] += t0.x * kvd; acc[1] += t0.y * kvd;
            acc[2] += t0.z * kvd; acc[3] += t0.w * kvd;
            acc[4] += t1.x * kvd; acc[5] += t1.y * kvd;
            acc[6] += t1.z * kvd; acc[7] += t1.w * kvd;
        }
        #pragma unroll
        for (int h = 0; h < 8; h++) sm[SU + a * 1056 + h * 132 + c] = acc[h];
    }
    __syncthreads();

    // ---- Phase H-mult: agg partials ; thread (g8 = d-octave, c4) ----
    {
        const int h = cc >> 4;   // all 4 columns share the head
        float4 a0 = make_float4(0.f,0.f,0.f,0.f), a1 = make_float4(0.f,0.f,0.f,0.f);
        #pragma unroll
        for (int i4 = 0; i4 < 4; i4++) {
            const float4 u0 = *(const float4*)&sm[SU + h * 132 + g8 * 16 + i4 * 4];
            const float4 u1 = *(const float4*)&sm[SU + 1056 + h * 132 + g8 * 16 + i4 * 4];
            #pragma unroll
            for (int t = 0; t < 4; t++) {
                const int d = g8 * 16 + i4 * 4 + t;
                const float4 wv = *(const float4*)&Wv[d * 128 + cc];
                const float us0 = (t==0)?u0.x:(t==1)?u0.y:(t==2)?u0.z:u0.w;
                const float us1 = (t==0)?u1.x:(t==1)?u1.y:(t==2)?u1.z:u1.w;
                a0.x += us0*wv.x; a0.y += us0*wv.y; a0.z += us0*wv.z; a0.w += us0*wv.w;
                a1.x += us1*wv.x; a1.y += us1*wv.y; a1.z += us1*wv.z; a1.w += us1*wv.w;
            }
        }
        __syncthreads();   // kv must be dead before overwriting partial region
        *(float4*)&sm[SKV + g8 * 256 + cc]       = a0;
        *(float4*)&sm[SKV + g8 * 256 + 128 + cc] = a1;
    }
    __syncthreads();

    // ---- H-reduce -> agg ----
    {
        float s = 0.f;
        #pragma unroll
        for (int d8 = 0; d8 < 8; d8++) s += sm[SKV + d8 * 256 + er * 128 + c];
        sm[SAGG + er * 128 + c] = s;
    }
    __syncthreads();

    // ---- Phase I-mult: out partials ----
    {
        float4 a0 = make_float4(0.f,0.f,0.f,0.f), a1 = make_float4(0.f,0.f,0.f,0.f);
        #pragma unroll
        for (int i4 = 0; i4 < 4; i4++) {
            const float4 x0 = *(const float4*)&sm[SAGG + g8 * 16 + i4 * 4];
            const float4 x1 = *(const float4*)&sm[SAGG + 128 + g8 * 16 + i4 * 4];
            #pragma unroll
            for (int t = 0; t < 4; t++) {
                const int e = g8 * 16 + i4 * 4 + t;
                const float4 wv = *(const float4*)&Wo[e * 128 + cc];
                const float xs0 = (t==0)?x0.x:(t==1)?x0.y:(t==2)?x0.z:x0.w;
                const float xs1 = (t==0)?x1.x:(t==1)?x1.y:(t==2)?x1.z:x1.w;
                a0.x += xs0*wv.x; a0.y += xs0*wv.y; a0.z += xs0*wv.z; a0.w += xs0*wv.w;
                a1.x += xs1*wv.x; a1.y += xs1*wv.y; a1.z += xs1*wv.z; a1.w += xs1*wv.w;
            }
        }
        __syncthreads();
        *(float4*)&sm[SKV + g8 * 256 + cc]       = a0;
        *(float4*)&sm[SKV + g8 * 256 + 128 + cc] = a1;
    }
    __syncthreads();

    // ---- I-reduce + residual -> out ----
    {
        float s = 0.f;
        #pragma unroll
        for (int e8 = 0; e8 < 8; e8++) s += sm[SKV + e8 * 256 + er * 128 + c];
        out[(atomBase + er) * D_ + c] = sm[SX + er * 128 + c] + s;
    }
}

} // namespace

extern "C" void kernel_launch(void* const* d_in, const int* in_sizes, int n_in,
                              void* d_out, int out_size) {
    (void)in_sizes; (void)n_in; (void)out_size;
    cudaFuncSetAttribute(tdt_kernel,
                         cudaFuncAttributeMaxDynamicSharedMemorySize, SMEM_BYTES);
    tdt_kernel<<<B_ * N_ / 2, 256, SMEM_BYTES>>>(
        (const float*)d_in[0],   // positions
        (const int*)  d_in[1],   // z
        (const int*)  d_in[2],   // neighbors
        (const float*)d_in[3],   // neighbor_mask
        (const float*)d_in[4],   // embedding
        (const float*)d_in[5],   // filt_W
        (const float*)d_in[6],   // filt_b
        (const float*)d_in[7],   // Wq
        (const float*)d_in[8],   // Wk
        (const float*)d_in[9],   // Wv
        (const float*)d_in[10],  // Wo
        (float*)d_out);
}

// round 8
// speedup vs baseline: 3.2995x; 1.4301x over previous
#include <cuda_runtime.h>
#include <cuda_fp16.h>
#include <cstdint>
#include <stdint.h>
#include <math.h>

namespace {

typedef unsigned int u32;

constexpr int B_  = 16;
constexpr int N_  = 512;
constexpr int K_  = 48;
constexpr int D_  = 128;
constexpr int KP1 = 49;

constexpr int KVH  = 136;             // half stride per kv row
constexpr int KVAH = KP1 * KVH;       // halfs per atom kv tile (6664)

// word offsets in dynamic smem
constexpr int SKV   = 0;       // kv half 2*6664 halfs = 6664 w ; alias: partials 2048 w
constexpr int SA    = 6664;    // f half tile 128 rows x 40 halfs = 2560 w  [B..E]
constexpr int SSC   = 6664;    // score partials 2048 w                     [F..softmax]
constexpr int SU    = 6664;    // u 2*8*132 = 2112 w                        [G..H]
constexpr int SATT  = 8776;    // attn transposed float 2*49*12 = 1176 w    [softmax..G]
constexpr int SB    = 9224;    // filtW half 32 x 136 = 2176 w -> ends 11400 [start..E]
constexpr int SP    = 9224;    // p float 2*8*132 = 2112 w (aliases SB)      [D..F]
constexpr int SX    = 11400;   // 256   (AFTER SB end — was the R7 bug)
constexpr int SQ    = 11656;   // 256
constexpr int SAGG  = 11912;   // 256
constexpr int SC_   = 12168;   // 128
constexpr int SLR   = 12296;   // 128
constexpr int SMK   = 12424;   // 128
constexpr int SZJ   = 12552;   // 128 ints
constexpr int SMEM_FLOATS = 12680;
constexpr int SMEM_BYTES  = SMEM_FLOATS * 4;   // 50720

__device__ __forceinline__ void ldsm4(u32* r, u32 a) {
    asm volatile("ldmatrix.sync.aligned.m8n8.x4.shared.b16 {%0,%1,%2,%3}, [%4];"
        : "=r"(r[0]), "=r"(r[1]), "=r"(r[2]), "=r"(r[3]) : "r"(a));
}
__device__ __forceinline__ void ldsm4t(u32* r, u32 a) {
    asm volatile("ldmatrix.sync.aligned.m8n8.x4.trans.shared.b16 {%0,%1,%2,%3}, [%4];"
        : "=r"(r[0]), "=r"(r[1]), "=r"(r[2]), "=r"(r[3]) : "r"(a));
}
__device__ __forceinline__ void mma16816(float* acc, const u32* a,
                                         u32 b0, u32 b1) {
    asm volatile(
        "mma.sync.aligned.m16n8k16.row.col.f32.f16.f16.f32 "
        "{%0,%1,%2,%3}, {%4,%5,%6,%7}, {%8,%9}, {%0,%1,%2,%3};"
        : "+f"(acc[0]), "+f"(acc[1]), "+f"(acc[2]), "+f"(acc[3])
        : "r"(a[0]), "r"(a[1]), "r"(a[2]), "r"(a[3]), "r"(b0), "r"(b1));
}
__device__ __forceinline__ u32 smem_u32(const void* p) {
    return (u32)__cvta_generic_to_shared(const_cast<void*>(p));
}

__global__ void __launch_bounds__(256, 4)
tdt_kernel(const float* __restrict__ positions,
           const int*   __restrict__ z,
           const int*   __restrict__ neighbors,
           const float* __restrict__ nmask,
           const float* __restrict__ embedding,
           const float* __restrict__ filtW,
           const float* __restrict__ filtb,
           const float* __restrict__ Wq,
           const float* __restrict__ Wk,
           const float* __restrict__ Wv,
           const float* __restrict__ Wo,
           float*       __restrict__ out)
{
    extern __shared__ __align__(16) float sm[];
    int*    smi = (int*)sm;
    __half* kvh = (__half*)sm;            // kv tile at word 0

    const int tid  = threadIdx.x;
    const int lane = tid & 31;
    const int warp = tid >> 5;
    const int c    = tid & 127;
    const int er   = tid >> 7;
    const int c4   = tid & 31;
    const int g8   = tid >> 5;
    const int cc   = c4 * 4;

    const int atomBase = blockIdx.x * 2;

    // center embeddings
    sm[SX + er * 128 + c] = embedding[z[atomBase + er] * D_ + c];

    // ---- filtW -> half B tile (stride 136) ----
    {
        __half* bb = (__half*)sm + SB * 2;
        for (int idx = tid; idx < 32 * 128; idx += 256) {
            const int g = idx >> 7, n = idx & 127;
            bb[g * 136 + n] = __float2half(filtW[idx]);
        }
    }

    // ---- Phase A: per-neighbor scalars ----
    if (tid < 128) {
        const int a = tid >> 6;
        const int j = tid & 63;
        if (j < KP1) {
            const int atom = atomBase + a;
            const int b    = atom >> 9;
            float r, mk; int zjv;
            if (j == 0) { r = 0.01f; mk = 1.0f; zjv = z[atom]; }
            else {
                const int nb = neighbors[atom * K_ + j - 1];
                const float dx = positions[(b * N_ + nb) * 3 + 0] - positions[atom * 3 + 0];
                const float dy = positions[(b * N_ + nb) * 3 + 1] - positions[atom * 3 + 1];
                const float dz = positions[(b * N_ + nb) * 3 + 2] - positions[atom * 3 + 2];
                r   = sqrtf(dx * dx + dy * dy + dz * dz + 1e-12f);
                mk  = nmask[atom * K_ + j - 1];
                zjv = z[b * N_ + nb];
            }
            sm[SLR + a * 64 + j] = __logf(r);
            sm[SC_ + a * 64 + j] = (r < 5.0f) ? (0.5f * (__cosf(r * 0.6283185307f) + 1.0f)) : 0.0f;
            sm[SMK + a * 64 + j] = mk;
            smi[SZJ + a * 64 + j] = zjv;
        }
    }
    __syncthreads();

    // ---- Phase B: gaussians -> fp16 A tile (row = a*64+j, stride 40 halfs) ----
    {
        const float OFF0  = -2.3025850930f;
        const float STEP  =  0.1261942905f;
        const float COEFF = -0.5f / (STEP * STEP);
        __half2* ah = (__half2*)sm;       // half2 index == word index
        for (int idx = tid; idx < 2 * KP1 * 16; idx += 256) {
            const int a   = idx / 784;
            const int rem = idx - a * 784;
            const int j   = rem >> 4;
            const int gp  = rem & 15;
            const float lr = sm[SLR + a * 64 + j];
            const float o0 = OFF0 + STEP * (float)(2 * gp);
            const float d0 = lr - o0;
            const float d1 = lr - (o0 + STEP);
            ah[SA + (a * 64 + j) * 20 + gp] =
                __floats2half2_rn(__expf(COEFF * d0 * d0), __expf(COEFF * d1 * d1));
        }
        // zero pad rows 49..63 of each atom
        for (int idx = tid; idx < 2 * 15 * 16; idx += 256) {
            const int a   = idx / 240;
            const int rem = idx - a * 240;
            const int j   = 49 + (rem >> 4);
            const int gp  = rem & 15;
            ah[SA + (a * 64 + j) * 20 + gp] = __floats2half2_rn(0.f, 0.f);
        }
    }
    {   // C-mult: q partials
        float4 a0 = make_float4(0.f,0.f,0.f,0.f), a1 = make_float4(0.f,0.f,0.f,0.f);
        #pragma unroll
        for (int i4 = 0; i4 < 4; i4++) {
            const float4 x0 = *(const float4*)&sm[SX + g8 * 16 + i4 * 4];
            const float4 x1 = *(const float4*)&sm[SX + 128 + g8 * 16 + i4 * 4];
            #pragma unroll
            for (int t = 0; t < 4; t++) {
                const int e = g8 * 16 + i4 * 4 + t;
                const float4 wv = *(const float4*)&Wq[e * 128 + cc];
                const float xs0 = (t==0)?x0.x:(t==1)?x0.y:(t==2)?x0.z:x0.w;
                const float xs1 = (t==0)?x1.x:(t==1)?x1.y:(t==2)?x1.z:x1.w;
                a0.x += xs0*wv.x; a0.y += xs0*wv.y; a0.z += xs0*wv.z; a0.w += xs0*wv.w;
                a1.x += xs1*wv.x; a1.y += xs1*wv.y; a1.z += xs1*wv.z; a1.w += xs1*wv.w;
            }
        }
        *(float4*)&sm[SKV + g8 * 256 + cc]       = a0;
        *(float4*)&sm[SKV + g8 * 256 + 128 + cc] = a1;
    }
    __syncthreads();

    // ---- C-reduce -> q ----
    {
        float s = 0.f;
        #pragma unroll
        for (int e8 = 0; e8 < 8; e8++) s += sm[SKV + e8 * 256 + er * 128 + c];
        sm[SQ + er * 128 + c] = s;
    }
    __syncthreads();

    // ---- Phase E: tensor-core filter GEMM + epilogue -> kv (half) ----
    {
        const int wA   = warp >> 2;           // atom
        const int grp  = lane >> 2;
        const int tg   = lane & 3;
        const int jj0  = (warp & 3) * 16 + grp;
        const int jj1  = jj0 + 8;
        const bool ok0 = jj0 < KP1, ok1 = jj1 < KP1;
        const int   zj0 = ok0 ? smi[SZJ + wA * 64 + jj0] : 0;
        const int   zj1 = ok1 ? smi[SZJ + wA * 64 + jj1] : 0;
        const float Cc0 = ok0 ? sm[SC_ + wA * 64 + jj0] : 0.f;
        const float Cc1 = ok1 ? sm[SC_ + wA * 64 + jj1] : 0.f;
        const float* em0 = embedding + zj0 * D_;
        const float* em1 = embedding + zj1 * D_;
        __half* kvb = kvh + wA * KVAH;

        u32 afr[2][4];
        {
            const __half* ab = (const __half*)sm + SA * 2;
            const int lrow = warp * 16 + ((lane & 8) ? 8 : 0) + (lane & 7);
            const int lcol = (lane & 16) ? 8 : 0;
            ldsm4(afr[0], smem_u32(ab + lrow * 40 + lcol));
            ldsm4(afr[1], smem_u32(ab + lrow * 40 + 16 + lcol));
        }
        const __half* bb = (const __half*)sm + SB * 2;
        const int brow = ((lane & 8) ? 8 : 0) + (lane & 7);
        const int bcol = (lane & 16) ? 8 : 0;

        #pragma unroll
        for (int np = 0; np < 8; np++) {
            float acc[8] = {0.f,0.f,0.f,0.f,0.f,0.f,0.f,0.f};
            #pragma unroll
            for (int kk = 0; kk < 2; kk++) {
                u32 bfr[4];
                ldsm4t(bfr, smem_u32(bb + (kk * 16 + brow) * 136 + np * 16 + bcol));
                mma16816(acc + 0, afr[kk], bfr[0], bfr[1]);
                mma16816(acc + 4, afr[kk], bfr[2], bfr[3]);
            }
            #pragma unroll
            for (int t = 0; t < 2; t++) {
                const int c0 = np * 16 + t * 8 + tg * 2;
                const float2 fb2 = *(const float2*)&filtb[c0];
                if (ok0) {
                    const float2 e2 = *(const float2*)&em0[c0];
                    const float v0 = (acc[t*4+0] + fb2.x) * Cc0 * e2.x;
                    const float v1 = (acc[t*4+1] + fb2.y) * Cc0 * e2.y;
                    *(__half2*)&kvb[jj0 * KVH + c0] = __floats2half2_rn(v0, v1);
                }
                if (ok1) {
                    const float2 e2 = *(const float2*)&em1[c0];
                    const float v0 = (acc[t*4+2] + fb2.x) * Cc1 * e2.x;
                    const float v1 = (acc[t*4+3] + fb2.y) * Cc1 * e2.y;
                    *(__half2*)&kvb[jj1 * KVH + c0] = __floats2half2_rn(v0, v1);
                }
            }
        }
    }
    __syncthreads();

    // ---- Phase D: p_a[h][d] = sum_e Wk[d][e] q_a[e] (into dead filtW region) ----
    {
        const float4 q0 = *(const float4*)&sm[SQ + lane * 4];
        const float4 q1 = *(const float4*)&sm[SQ + 128 + lane * 4];
        #pragma unroll
        for (int rr = 0; rr < 16; rr++) {
            const int d = warp * 16 + rr;
            const float4 wr = *(const float4*)&Wk[d * D_ + lane * 4];
            float p0 = wr.x * q0.x + wr.y * q0.y + wr.z * q0.z + wr.w * q0.w;
            float p1 = wr.x * q1.x + wr.y * q1.y + wr.z * q1.z + wr.w * q1.w;
            p0 += __shfl_xor_sync(0xffffffffu, p0, 1);
            p0 += __shfl_xor_sync(0xffffffffu, p0, 2);
            p1 += __shfl_xor_sync(0xffffffffu, p1, 1);
            p1 += __shfl_xor_sync(0xffffffffu, p1, 2);
            if ((lane & 3) == 0) {
                const int h = lane >> 2;
                sm[SP + h * 132 + d]        = p0;
                sm[SP + 1056 + h * 132 + d] = p1;
            }
        }
    }
    __syncthreads();

    // ---- Phase F: partial scores; kv read once ----
    {
        const int task  = warp >> 1;
        const int a     = task >> 1;
        const int rep   = task & 1;
        const int dhalf = warp & 1;
        const int j     = rep * 32 + lane;
        float acc[8];
        #pragma unroll
        for (int h = 0; h < 8; h++) acc[h] = 0.f;
        if (j < KP1) {
            const uint4* kvr = (const uint4*)&kvh[a * KVAH + j * KVH + dhalf * 64];
            const float* pb  = &sm[SP + a * 1056 + dhalf * 64];
            #pragma unroll
            for (int c8 = 0; c8 < 8; c8++) {
                const uint4 raw = kvr[c8];
                const float2 f01 = __half22float2(*(const __half2*)&raw.x);
                const float2 f23 = __half22float2(*(const __half2*)&raw.y);
                const float2 f45 = __half22float2(*(const __half2*)&raw.z);
                const float2 f67 = __half22float2(*(const __half2*)&raw.w);
                #pragma unroll
                for (int h = 0; h < 8; h++) {
                    const float4 p0 = *(const float4*)&pb[h * 132 + c8 * 8];
                    const float4 p1 = *(const float4*)&pb[h * 132 + c8 * 8 + 4];
                    acc[h] += f01.x*p0.x + f01.y*p0.y + f23.x*p0.z + f23.y*p0.w
                            + f45.x*p1.x + f45.y*p1.y + f67.x*p1.z + f67.y*p1.w;
                }
            }
        }
        #pragma unroll
        for (int h = 0; h < 8; h++)
            sm[SSC + ((task * 2 + dhalf) * 8 + h) * 32 + lane] = acc[h];
    }
    __syncthreads();

    // ---- softmax: warp = head; writes TRANSPOSED attn [j][h] stride 12 ----
    {
        const int h = warp;
        #pragma unroll
        for (int a = 0; a < 2; a++) {
            const int t0 = a * 2, t1 = a * 2 + 1;
            float v0 = sm[SSC + ((t0*2+0)*8 + h)*32 + lane]
                     + sm[SSC + ((t0*2+1)*8 + h)*32 + lane];
            float v1 = (lane < 17) ? sm[SSC + ((t1*2+0)*8 + h)*32 + lane]
                                   + sm[SSC + ((t1*2+1)*8 + h)*32 + lane] : 0.f;
            v0 = (sm[SMK + a * 64 + lane] > 0.f) ? v0 * 0.25f : -1e9f;
            const int j1 = lane + 32;
            if (j1 < KP1) v1 = (sm[SMK + a * 64 + j1] > 0.f) ? v1 * 0.25f : -1e9f;
            else          v1 = -3.0e38f;
            float m = fmaxf(v0, v1);
            #pragma unroll
            for (int o = 16; o > 0; o >>= 1)
                m = fmaxf(m, __shfl_xor_sync(0xffffffffu, m, o));
            const float e0 = __expf(v0 - m);
            const float e1 = (j1 < KP1) ? __expf(v1 - m) : 0.f;
            float ssum = e0 + e1;
            #pragma unroll
            for (int o = 16; o > 0; o >>= 1)
                ssum += __shfl_xor_sync(0xffffffffu, ssum, o);
            const float inv = 1.0f / ssum;
            sm[SATT + a * 588 + lane * 12 + h] = e0 * inv;
            if (j1 < KP1) sm[SATT + a * 588 + j1 * 12 + h] = e1 * inv;
        }
    }
    __syncthreads();

    // ---- Phase G: u[a][h][c] = sum_j attn[j][h] * kv[j][c] ----
    {
        const int a = er;
        const __half* kvc = &kvh[a * KVAH + c];
        const float*  atb = &sm[SATT + a * 588];
        float acc[8];
        #pragma unroll
        for (int h = 0; h < 8; h++) acc[h] = 0.f;
        #pragma unroll 7
        for (int j = 0; j < KP1; j++) {
            const float4 t0 = *(const float4*)&atb[j * 12];
            const float4 t1 = *(const float4*)&atb[j * 12 + 4];
            const float kvd = __half2float(kvc[j * KVH]);
            acc[0] += t0.x * kvd; acc[1] += t0.y * kvd;
            acc[2] += t0.z * kvd; acc[3] += t0.w * kvd;
            acc[4] += t1.x * kvd; acc[5] += t1.y * kvd;
            acc[6] += t1.z * kvd; acc[7] += t1.w * kvd;
        }
        #pragma unroll
        for (int h = 0; h < 8; h++) sm[SU + a * 1056 + h * 132 + c] = acc[h];
    }
    __syncthreads();

    // ---- Phase H-mult: agg partials ----
    {
        const int h = cc >> 4;
        float4 a0 = make_float4(0.f,0.f,0.f,0.f), a1 = make_float4(0.f,0.f,0.f,0.f);
        #pragma unroll
        for (int i4 = 0; i4 < 4; i4++) {
            const float4 u0 = *(const float4*)&sm[SU + h * 132 + g8 * 16 + i4 * 4];
            const float4 u1 = *(const float4*)&sm[SU + 1056 + h * 132 + g8 * 16 + i4 * 4];
            #pragma unroll
            for (int t = 0; t < 4; t++) {
                const int d = g8 * 16 + i4 * 4 + t;
                const float4 wv = *(const float4*)&Wv[d * 128 + cc];
                const float us0 = (t==0)?u0.x:(t==1)?u0.y:(t==2)?u0.z:u0.w;
                const float us1 = (t==0)?u1.x:(t==1)?u1.y:(t==2)?u1.z:u1.w;
                a0.x += us0*wv.x; a0.y += us0*wv.y; a0.z += us0*wv.z; a0.w += us0*wv.w;
                a1.x += us1*wv.x; a1.y += us1*wv.y; a1.z += us1*wv.z; a1.w += us1*wv.w;
            }
        }
        *(float4*)&sm[SKV + g8 * 256 + cc]       = a0;   // kv dead (G done)
        *(float4*)&sm[SKV + g8 * 256 + 128 + cc] = a1;
    }
    __syncthreads();

    // ---- H-reduce -> agg ----
    {
        float s = 0.f;
        #pragma unroll
        for (int d8 = 0; d8 < 8; d8++) s += sm[SKV + d8 * 256 + er * 128 + c];
        sm[SAGG + er * 128 + c] = s;
    }
    __syncthreads();

    // ---- Phase I-mult: out partials ----
    {
        float4 a0 = make_float4(0.f,0.f,0.f,0.f), a1 = make_float4(0.f,0.f,0.f,0.f);
        #pragma unroll
        for (int i4 = 0; i4 < 4; i4++) {
            const float4 x0 = *(const float4*)&sm[SAGG + g8 * 16 + i4 * 4];
            const float4 x1 = *(const float4*)&sm[SAGG + 128 + g8 * 16 + i4 * 4];
            #pragma unroll
            for (int t = 0; t < 4; t++) {
                const int e = g8 * 16 + i4 * 4 + t;
                const float4 wv = *(const float4*)&Wo[e * 128 + cc];
                const float xs0 = (t==0)?x0.x:(t==1)?x0.y:(t==2)?x0.z:x0.w;
                const float xs1 = (t==0)?x1.x:(t==1)?x1.y:(t==2)?x1.z:x1.w;
                a0.x += xs0*wv.x; a0.y += xs0*wv.y; a0.z += xs0*wv.z; a0.w += xs0*wv.w;
                a1.x += xs1*wv.x; a1.y += xs1*wv.y; a1.z += xs1*wv.z; a1.w += xs1*wv.w;
            }
        }
        __syncthreads();
        *(float4*)&sm[SKV + g8 * 256 + cc]       = a0;
        *(float4*)&sm[SKV + g8 * 256 + 128 + cc] = a1;
    }
    __syncthreads();

    // ---- I-reduce + residual -> out ----
    {
        float s = 0.f;
        #pragma unroll
        for (int e8 = 0; e8 < 8; e8++) s += sm[SKV + e8 * 256 + er * 128 + c];
        out[(atomBase + er) * D_ + c] = sm[SX + er * 128 + c] + s;
    }
}

} // namespace

extern "C" void kernel_launch(void* const* d_in, const int* in_sizes, int n_in,
                              void* d_out, int out_size) {
    (void)in_sizes; (void)n_in; (void)out_size;
    cudaFuncSetAttribute(tdt_kernel,
                         cudaFuncAttributeMaxDynamicSharedMemorySize, SMEM_BYTES);
    tdt_kernel<<<B_ * N_ / 2, 256, SMEM_BYTES>>>(
        (const float*)d_in[0],   // positions
        (const int*)  d_in[1],   // z
        (const int*)  d_in[2],   // neighbors
        (const float*)d_in[3],   // neighbor_mask
        (const float*)d_in[4],   // embedding
        (const float*)d_in[5],   // filt_W
        (const float*)d_in[6],   // filt_b
        (const float*)d_in[7],   // Wq
        (const float*)d_in[8],   // Wk
        (const float*)d_in[9],   // Wv
        (const float*)d_in[10],  // Wo
        (float*)d_out);
}